// round 15
// baseline (speedup 1.0000x reference)
#include <cuda_runtime.h>
#include <cuda_fp16.h>
#include <stdint.h>

// Hybrid_Conv2d via warp-level mma.sync fp16 (m16n8k16) implicit GEMM.
// out[b] = conv2d(x[b], W0 + cov[b]*W1), 3x3 pad 1, B=32, C=64, 128x128.
//
// R14: R13 persistent structure, ONE change: 512 threads / 16 warps per CTA
//      (warp tile m32xn64 instead of m64xn64) -> 4 warps/SMSP to hide
//      sync/staging/retire gaps that pinned the tensor pipe at 58%.
//  - CTA tile = (batch b, 4 image rows); warp = 32 px x 64 cout.
//  - sA: [780 pos][32 kw + pad]; sB: [9 tap][64 co][32 kw + pad]; row stride
//    144B (mod 128 == 16) -> ldmatrix conflict-free.

#define HW_   128
#define C_    64
#define B_    32
#define NT    512                // 16 warps
#define NTP   256                // prologue threads
#define NTILES 1024              // 32 batches x 32 row-tiles
#define GRID_P 152               // GB300 SM count

#define SA_POS    780            // 6 halo rows x 130 cols
#define ROWB      144            // 128B data + 16B pad
#define SA_BYTES  (SA_POS * ROWB)     // 112320
#define SB_ROWS   (9 * 64)            // tap x co
#define SB_BYTES  (SB_ROWS * ROWB)    // 82944
#define SMEM_BYTES (SA_BYTES + SB_BYTES)   // 195264

__device__ __half   d_xh[(size_t)B_ * HW_ * HW_ * C_];   // [b][y][x][ci]
__device__ uint32_t d_Wcp[B_ * 9 * C_ * 32];  // [b][tap][co][kw], fp16x2(ci pair)

static __device__ __forceinline__ uint32_t smem_u32(const void* p) {
    uint32_t a;
    asm("{ .reg .u64 t; cvta.to.shared.u64 t, %1; cvt.u32.u64 %0, t; }" : "=r"(a) : "l"(p));
    return a;
}
static __device__ __forceinline__ void cp16(uint32_t dst, const void* src, int sz) {
    asm volatile("cp.async.cg.shared.global [%0], [%1], 16, %2;"
                 :: "r"(dst), "l"(src), "r"(sz) : "memory");
}
template <int N> static __device__ __forceinline__ void cp_wait() {
    asm volatile("cp.async.wait_group %0;" :: "n"(N) : "memory");
}
static __device__ __forceinline__ uint32_t packh2(float lo, float hi) {
    __half2 h = __floats2half2_rn(lo, hi);
    return *reinterpret_cast<uint32_t*>(&h);
}
#define LDSM_X4(r0, r1, r2, r3, addr)                                        \
    asm volatile("ldmatrix.sync.aligned.m8n8.x4.shared.b16 {%0,%1,%2,%3}, [%4];" \
        : "=r"(r0), "=r"(r1), "=r"(r2), "=r"(r3) : "r"(addr))

// ---- fused prologue: transpose x to channels-last fp16 + build weights ----
// (identical to R10/R12/R13)
__global__ void prologue_kernel(const float* __restrict__ x,
                                const float* __restrict__ W0,
                                const float* __restrict__ W1,
                                const float* __restrict__ cov) {
    const int b = blockIdx.y;
    if (blockIdx.x < HW_) {
        __shared__ float sT[C_][HW_ + 1];
        const int y = blockIdx.x;
        const float4* src = (const float4*)(x + ((size_t)(b * C_) * HW_ + y) * HW_);
        for (int e = threadIdx.x; e < C_ * (HW_ / 4); e += NTP) {
            const int ci = e >> 5, xq = e & 31;
            float4 v = src[(size_t)ci * (HW_ * HW_ / 4) + xq];
            sT[ci][xq * 4]     = v.x;
            sT[ci][xq * 4 + 1] = v.y;
            sT[ci][xq * 4 + 2] = v.z;
            sT[ci][xq * 4 + 3] = v.w;
        }
        __syncthreads();
        uint32_t* dst = (uint32_t*)(d_xh + ((size_t)(b * HW_) + y) * HW_ * C_);
        for (int e = threadIdx.x; e < HW_ * 32; e += NTP) {
            const int xx = e >> 5, kw = e & 31;
            dst[xx * 32 + kw] = packh2(sT[2 * kw][xx], sT[2 * kw + 1][xx]);
        }
    } else {
        const int tap = blockIdx.x - HW_;     // 0..8
        const float cv = cov[b];
        for (int i = threadIdx.x; i < C_ * 32; i += NTP) {
            const int co = i >> 5, kw = i & 31;
            const int g0 = (co * C_ + 2 * kw) * 9 + tap;
            d_Wcp[((b * 9 + tap) * C_ + co) * 32 + kw] =
                packh2(W0[g0] + cv * W1[g0], W0[g0 + 9] + cv * W1[g0 + 9]);
        }
    }
}

extern __shared__ uint32_t smem_dyn[];

__global__ __launch_bounds__(NT, 1)
void hybrid_conv_mma_kernel(float* __restrict__ out) {
    const int tid = threadIdx.x;
    const int wa  = tid >> 5;          // warp 0..15
    const int lid = tid & 31;
    const int g   = lid >> 2;
    const int ti  = lid & 3;

    const uint32_t sa_base = smem_u32(smem_dyn);
    const uint32_t sb_base = sa_base + SA_BYTES;

    auto stageA4 = [&](int bn, int y0n, int chb) {
        for (int q = tid; q < SA_POS * 4; q += NT) {
            const int pos = q >> 2, ch = (q & 3) + chb;
            const int r = pos / 130, c = pos - r * 130;
            const int gy = y0n - 1 + r, gx = c - 1;
            const bool ok = ((unsigned)gy < (unsigned)HW_) & ((unsigned)gx < (unsigned)HW_);
            const __half* src = d_xh + (((size_t)(bn * HW_ + (ok ? gy : 0)) * HW_
                                   + (ok ? gx : 0)) * C_ + ch * 8);
            cp16(sa_base + pos * ROWB + ch * 16, src, ok ? 16 : 0);
        }
    };
    auto stageB = [&](int bn) {
        for (int q = tid; q < SB_ROWS * 8; q += NT) {
            const int row = q >> 3, ch = q & 7;
            cp16(sb_base + row * ROWB + ch * 16,
                 d_Wcp + ((size_t)(bn * SB_ROWS) + row) * 32 + ch * 4, 16);
        }
    };

    // per-lane ldmatrix address components
    // warp tile: image row (wa>>2), cols (wa&3)*32 .. +32 ; m-tiles mt=0,1
    const int pwarp  = (wa >> 2) * 130 + (wa & 3) * 32;
    const uint32_t laneA  = (uint32_t)((lid & 15) * ROWB + ((lid & 16) ? 16 : 0));
    const int      laneBc = (lid & 7) + ((lid >> 4) << 3);
    const uint32_t laneBk = (lid & 8) ? 16u : 0u;

    // ---- first tile: 2-group staged ----
    int t = blockIdx.x;
    {
        const int bn = t >> 5, y0n = (t & 31) * 4;
        stageB(bn);
        stageA4(bn, y0n, 0);
        asm volatile("cp.async.commit_group;" ::: "memory");
        stageA4(bn, y0n, 4);
        asm volatile("cp.async.commit_group;" ::: "memory");
    }

    bool first = true;
    while (t < NTILES) {
        const int b  = t >> 5;
        const int y0 = (t & 31) * 4;

        float acc[2][8][4];
        #pragma unroll
        for (int mt = 0; mt < 2; mt++)
            #pragma unroll
            for (int nt = 0; nt < 8; nt++)
                #pragma unroll
                for (int r = 0; r < 4; r++) acc[mt][nt][r] = 0.0f;

        #pragma unroll
        for (int half = 0; half < 2; half++) {
            if (first) {
                if (half == 0) cp_wait<1>(); else cp_wait<0>();
                __syncthreads();
            } else if (half == 0) {
                cp_wait<0>();
                __syncthreads();
            }

            #pragma unroll 1
            for (int tap = 0; tap < 9; tap++) {
                const int ky = tap / 3;
                const int pb = pwarp + ky * 130 + (tap - ky * 3);
                const uint32_t sbt = sb_base + (uint32_t)(tap * 64 * ROWB);
                #pragma unroll
                for (int ks2 = 0; ks2 < 2; ks2++) {
                    const uint32_t kbyte = (uint32_t)((half * 2 + ks2) * 32);

                    // ---- fragment loads: 2 A + 4 B back-to-back ----
                    uint32_t a[2][4], bf[4][4];
                    #pragma unroll
                    for (int mt = 0; mt < 2; mt++) {
                        const uint32_t ad = sa_base
                            + (uint32_t)((pb + mt * 16) * ROWB) + kbyte + laneA;
                        LDSM_X4(a[mt][0], a[mt][1], a[mt][2], a[mt][3], ad);
                    }
                    #pragma unroll
                    for (int q = 0; q < 4; q++) {
                        const uint32_t bd = sbt
                            + (uint32_t)((16 * q + laneBc) * ROWB) + kbyte + laneBk;
                        LDSM_X4(bf[q][0], bf[q][1], bf[q][2], bf[q][3], bd);
                    }

                    // ---- 16 MMAs, no interleaved loads ----
                    #pragma unroll
                    for (int q = 0; q < 4; q++) {
                        #pragma unroll
                        for (int mt = 0; mt < 2; mt++) {
                            asm volatile(
                                "mma.sync.aligned.m16n8k16.row.col.f32.f16.f16.f32 "
                                "{%0,%1,%2,%3}, {%4,%5,%6,%7}, {%8,%9}, {%0,%1,%2,%3};"
                                : "+f"(acc[mt][2 * q][0]), "+f"(acc[mt][2 * q][1]),
                                  "+f"(acc[mt][2 * q][2]), "+f"(acc[mt][2 * q][3])
                                : "r"(a[mt][0]), "r"(a[mt][1]), "r"(a[mt][2]),
                                  "r"(a[mt][3]), "r"(bf[q][0]), "r"(bf[q][1]));
                        }
                        #pragma unroll
                        for (int mt = 0; mt < 2; mt++) {
                            asm volatile(
                                "mma.sync.aligned.m16n8k16.row.col.f32.f16.f16.f32 "
                                "{%0,%1,%2,%3}, {%4,%5,%6,%7}, {%8,%9}, {%0,%1,%2,%3};"
                                : "+f"(acc[mt][2 * q + 1][0]), "+f"(acc[mt][2 * q + 1][1]),
                                  "+f"(acc[mt][2 * q + 1][2]), "+f"(acc[mt][2 * q + 1][3])
                                : "r"(a[mt][0]), "r"(a[mt][1]), "r"(a[mt][2]),
                                  "r"(a[mt][3]), "r"(bf[q][2]), "r"(bf[q][3]));
                        }
                    }
                }
            }
        }

        // ---- prefetch next tile's slab ----
        __syncthreads();
        const int tn = t + GRID_P;
        if (tn < NTILES) {
            const int bn = tn >> 5, y0n = (tn & 31) * 4;
            stageB(bn);
            stageA4(bn, y0n, 0);
            stageA4(bn, y0n, 4);
            asm volatile("cp.async.commit_group;" ::: "memory");
        }

        // ---- epilogue ----
        {
            const int row   = y0 + (wa >> 2);
            const int cbase = (wa & 3) * 32;
            #pragma unroll
            for (int mt = 0; mt < 2; mt++) {
                const int col = cbase + mt * 16 + g;
                #pragma unroll
                for (int nt = 0; nt < 8; nt++) {
                    const int n = nt * 8 + 2 * ti;
                    float* op = out + (((size_t)(b * C_ + n) * HW_) + row) * HW_;
                    op[col]                 = acc[mt][nt][0];
                    op[HW_ * HW_ + col]     = acc[mt][nt][1];   // cout n+1
                    op[col + 8]             = acc[mt][nt][2];
                    op[HW_ * HW_ + col + 8] = acc[mt][nt][3];
                }
            }
        }

        t = tn;
        first = false;
    }
}

extern "C" void kernel_launch(void* const* d_in, const int* in_sizes, int n_in,
                              void* d_out, int out_size) {
    (void)in_sizes; (void)n_in; (void)out_size;
    const float* x   = (const float*)d_in[0];
    const float* cov = (const float*)d_in[1];
    const float* W0  = (const float*)d_in[2];
    const float* W1  = (const float*)d_in[3];
    float* out = (float*)d_out;

    prologue_kernel<<<dim3(HW_ + 9, B_), NTP>>>(x, W0, W1, cov);

    cudaFuncSetAttribute(hybrid_conv_mma_kernel,
                         cudaFuncAttributeMaxDynamicSharedMemorySize, SMEM_BYTES);
    hybrid_conv_mma_kernel<<<dim3(GRID_P), NT, SMEM_BYTES>>>(out);
}

// round 16
// speedup vs baseline: 1.0362x; 1.0362x over previous
#include <cuda_runtime.h>
#include <cuda_fp16.h>
#include <stdint.h>

// Hybrid_Conv2d via warp-level mma.sync fp16 (m16n8k16) implicit GEMM.
// out[b] = conv2d(x[b], W0 + cov[b]*W1), 3x3 pad 1, B=32, C=64, 128x128.
//
// R15: main = R13 (persistent 8-warp CTAs, hoisted fragments) with a uniform
//      2-group prefetch (half0 waits only the first group); prologue stores
//      vectorized to uint4.
//  - CTA tile = (batch b, 4 image rows), 8 warps: warp = 64 px x 64 cout.
//  - sA: [780 pos][32 kw + pad]; sB: [9 tap][64 co][32 kw + pad]; row stride
//    144B (mod 128 == 16) -> ldmatrix conflict-free.

#define HW_   128
#define C_    64
#define B_    32
#define NT    256
#define NTP   256                // prologue threads
#define NTILES 1024              // 32 batches x 32 row-tiles
#define GRID_P 152               // GB300 SM count

#define SA_POS    780            // 6 halo rows x 130 cols
#define ROWB      144            // 128B data + 16B pad
#define SA_BYTES  (SA_POS * ROWB)     // 112320
#define SB_ROWS   (9 * 64)            // tap x co
#define SB_BYTES  (SB_ROWS * ROWB)    // 82944
#define SMEM_BYTES (SA_BYTES + SB_BYTES)   // 195264

__device__ __half   d_xh[(size_t)B_ * HW_ * HW_ * C_];   // [b][y][x][ci]
__device__ uint32_t d_Wcp[B_ * 9 * C_ * 32];  // [b][tap][co][kw], fp16x2(ci pair)

static __device__ __forceinline__ uint32_t smem_u32(const void* p) {
    uint32_t a;
    asm("{ .reg .u64 t; cvta.to.shared.u64 t, %1; cvt.u32.u64 %0, t; }" : "=r"(a) : "l"(p));
    return a;
}
static __device__ __forceinline__ void cp16(uint32_t dst, const void* src, int sz) {
    asm volatile("cp.async.cg.shared.global [%0], [%1], 16, %2;"
                 :: "r"(dst), "l"(src), "r"(sz) : "memory");
}
template <int N> static __device__ __forceinline__ void cp_wait() {
    asm volatile("cp.async.wait_group %0;" :: "n"(N) : "memory");
}
static __device__ __forceinline__ uint32_t packh2(float lo, float hi) {
    __half2 h = __floats2half2_rn(lo, hi);
    return *reinterpret_cast<uint32_t*>(&h);
}
#define LDSM_X4(r0, r1, r2, r3, addr)                                        \
    asm volatile("ldmatrix.sync.aligned.m8n8.x4.shared.b16 {%0,%1,%2,%3}, [%4];" \
        : "=r"(r0), "=r"(r1), "=r"(r2), "=r"(r3) : "r"(addr))

// ---- fused prologue: transpose x to channels-last fp16 + build weights ----
// uint4-vectorized stores on the d_xh stream.
__global__ void prologue_kernel(const float* __restrict__ x,
                                const float* __restrict__ W0,
                                const float* __restrict__ W1,
                                const float* __restrict__ cov) {
    const int b = blockIdx.y;
    if (blockIdx.x < HW_) {
        __shared__ float sT[C_][HW_ + 1];
        const int y = blockIdx.x;
        const float4* src = (const float4*)(x + ((size_t)(b * C_) * HW_ + y) * HW_);
        for (int e = threadIdx.x; e < C_ * (HW_ / 4); e += NTP) {
            const int ci = e >> 5, xq = e & 31;
            float4 v = src[(size_t)ci * (HW_ * HW_ / 4) + xq];
            sT[ci][xq * 4]     = v.x;
            sT[ci][xq * 4 + 1] = v.y;
            sT[ci][xq * 4 + 2] = v.z;
            sT[ci][xq * 4 + 3] = v.w;
        }
        __syncthreads();
        uint4* dst = (uint4*)(d_xh + ((size_t)(b * HW_) + y) * HW_ * C_);
        for (int e = threadIdx.x; e < HW_ * 8; e += NTP) {
            const int xx = e >> 3, kq = e & 7;   // kq = group of 4 kw
            uint4 w;
            w.x = packh2(sT[8 * kq    ][xx], sT[8 * kq + 1][xx]);
            w.y = packh2(sT[8 * kq + 2][xx], sT[8 * kq + 3][xx]);
            w.z = packh2(sT[8 * kq + 4][xx], sT[8 * kq + 5][xx]);
            w.w = packh2(sT[8 * kq + 6][xx], sT[8 * kq + 7][xx]);
            dst[xx * 8 + kq] = w;
        }
    } else {
        const int tap = blockIdx.x - HW_;     // 0..8
        const float cv = cov[b];
        for (int i = threadIdx.x; i < C_ * 32; i += NTP) {
            const int co = i >> 5, kw = i & 31;
            const int g0 = (co * C_ + 2 * kw) * 9 + tap;
            d_Wcp[((b * 9 + tap) * C_ + co) * 32 + kw] =
                packh2(W0[g0] + cv * W1[g0], W0[g0 + 9] + cv * W1[g0 + 9]);
        }
    }
}

extern __shared__ uint32_t smem_dyn[];

__global__ __launch_bounds__(NT, 1)
void hybrid_conv_mma_kernel(float* __restrict__ out) {
    const int tid = threadIdx.x;
    const int wa  = tid >> 5;
    const int lid = tid & 31;
    const int g   = lid >> 2;
    const int ti  = lid & 3;

    const uint32_t sa_base = smem_u32(smem_dyn);
    const uint32_t sb_base = sa_base + SA_BYTES;

    auto stageA4 = [&](int bn, int y0n, int chb) {
        for (int q = tid; q < SA_POS * 4; q += NT) {
            const int pos = q >> 2, ch = (q & 3) + chb;
            const int r = pos / 130, c = pos - r * 130;
            const int gy = y0n - 1 + r, gx = c - 1;
            const bool ok = ((unsigned)gy < (unsigned)HW_) & ((unsigned)gx < (unsigned)HW_);
            const __half* src = d_xh + (((size_t)(bn * HW_ + (ok ? gy : 0)) * HW_
                                   + (ok ? gx : 0)) * C_ + ch * 8);
            cp16(sa_base + pos * ROWB + ch * 16, src, ok ? 16 : 0);
        }
    };
    auto stageB = [&](int bn) {
        for (int q = tid; q < SB_ROWS * 8; q += NT) {
            const int row = q >> 3, ch = q & 7;
            cp16(sb_base + row * ROWB + ch * 16,
                 d_Wcp + ((size_t)(bn * SB_ROWS) + row) * 32 + ch * 4, 16);
        }
    };
    // 2-group prefetch: G1 = B + A ch0-3 (covers compute half 0),
    //                   G2 = A ch4-7 (half 1).
    auto prefetch = [&](int tt) {
        const int bn = tt >> 5, y0n = (tt & 31) * 4;
        stageB(bn);
        stageA4(bn, y0n, 0);
        asm volatile("cp.async.commit_group;" ::: "memory");
        stageA4(bn, y0n, 4);
        asm volatile("cp.async.commit_group;" ::: "memory");
    };

    // per-lane ldmatrix address components
    const int pwarp  = (wa >> 1) * 130 + (wa & 1) * 64;
    const uint32_t laneA  = (uint32_t)((lid & 15) * ROWB + ((lid & 16) ? 16 : 0));
    const int      laneBc = (lid & 7) + ((lid >> 4) << 3);
    const uint32_t laneBk = (lid & 8) ? 16u : 0u;

    int t = blockIdx.x;
    prefetch(t);

    while (t < NTILES) {
        const int b  = t >> 5;
        const int y0 = (t & 31) * 4;

        float acc[4][8][4];
        #pragma unroll
        for (int mt = 0; mt < 4; mt++)
            #pragma unroll
            for (int nt = 0; nt < 8; nt++)
                #pragma unroll
                for (int r = 0; r < 4; r++) acc[mt][nt][r] = 0.0f;

        #pragma unroll
        for (int half = 0; half < 2; half++) {
            if (half == 0) cp_wait<1>(); else cp_wait<0>();
            __syncthreads();

            #pragma unroll 1
            for (int tap = 0; tap < 9; tap++) {
                const int ky = tap / 3;
                const int pb = pwarp + ky * 130 + (tap - ky * 3);
                const uint32_t sbt = sb_base + (uint32_t)(tap * 64 * ROWB);
                #pragma unroll
                for (int ks2 = 0; ks2 < 2; ks2++) {
                    const uint32_t kbyte = (uint32_t)((half * 2 + ks2) * 32);

                    // hoisted fragment loads: 4 A + 4 B back-to-back
                    uint32_t a[4][4], bf[4][4];
                    #pragma unroll
                    for (int mt = 0; mt < 4; mt++) {
                        const uint32_t ad = sa_base
                            + (uint32_t)((pb + mt * 16) * ROWB) + kbyte + laneA;
                        LDSM_X4(a[mt][0], a[mt][1], a[mt][2], a[mt][3], ad);
                    }
                    #pragma unroll
                    for (int q = 0; q < 4; q++) {
                        const uint32_t bd = sbt
                            + (uint32_t)((16 * q + laneBc) * ROWB) + kbyte + laneBk;
                        LDSM_X4(bf[q][0], bf[q][1], bf[q][2], bf[q][3], bd);
                    }

                    // 32 MMAs, no interleaved loads
                    #pragma unroll
                    for (int q = 0; q < 4; q++) {
                        #pragma unroll
                        for (int mt = 0; mt < 4; mt++) {
                            asm volatile(
                                "mma.sync.aligned.m16n8k16.row.col.f32.f16.f16.f32 "
                                "{%0,%1,%2,%3}, {%4,%5,%6,%7}, {%8,%9}, {%0,%1,%2,%3};"
                                : "+f"(acc[mt][2 * q][0]), "+f"(acc[mt][2 * q][1]),
                                  "+f"(acc[mt][2 * q][2]), "+f"(acc[mt][2 * q][3])
                                : "r"(a[mt][0]), "r"(a[mt][1]), "r"(a[mt][2]),
                                  "r"(a[mt][3]), "r"(bf[q][0]), "r"(bf[q][1]));
                        }
                        #pragma unroll
                        for (int mt = 0; mt < 4; mt++) {
                            asm volatile(
                                "mma.sync.aligned.m16n8k16.row.col.f32.f16.f16.f32 "
                                "{%0,%1,%2,%3}, {%4,%5,%6,%7}, {%8,%9}, {%0,%1,%2,%3};"
                                : "+f"(acc[mt][2 * q + 1][0]), "+f"(acc[mt][2 * q + 1][1]),
                                  "+f"(acc[mt][2 * q + 1][2]), "+f"(acc[mt][2 * q + 1][3])
                                : "r"(a[mt][0]), "r"(a[mt][1]), "r"(a[mt][2]),
                                  "r"(a[mt][3]), "r"(bf[q][2]), "r"(bf[q][3]));
                        }
                    }
                }
            }
        }

        // ---- prefetch next tile's slab (after all reads of this slab) ----
        __syncthreads();
        const int tn = t + GRID_P;
        if (tn < NTILES) prefetch(tn);

        // ---- epilogue ----
        {
            const int row   = y0 + (wa >> 1);
            const int cbase = (wa & 1) * 64;
            #pragma unroll
            for (int mt = 0; mt < 4; mt++) {
                const int col = cbase + mt * 16 + g;
                #pragma unroll
                for (int nt = 0; nt < 8; nt++) {
                    const int n = nt * 8 + 2 * ti;
                    float* op = out + (((size_t)(b * C_ + n) * HW_) + row) * HW_;
                    op[col]                 = acc[mt][nt][0];
                    op[HW_ * HW_ + col]     = acc[mt][nt][1];   // cout n+1
                    op[col + 8]             = acc[mt][nt][2];
                    op[HW_ * HW_ + col + 8] = acc[mt][nt][3];
                }
            }
        }

        t = tn;
    }
}

extern "C" void kernel_launch(void* const* d_in, const int* in_sizes, int n_in,
                              void* d_out, int out_size) {
    (void)in_sizes; (void)n_in; (void)out_size;
    const float* x   = (const float*)d_in[0];
    const float* cov = (const float*)d_in[1];
    const float* W0  = (const float*)d_in[2];
    const float* W1  = (const float*)d_in[3];
    float* out = (float*)d_out;

    prologue_kernel<<<dim3(HW_ + 9, B_), NTP>>>(x, W0, W1, cov);

    cudaFuncSetAttribute(hybrid_conv_mma_kernel,
                         cudaFuncAttributeMaxDynamicSharedMemorySize, SMEM_BYTES);
    hybrid_conv_mma_kernel<<<dim3(GRID_P), NT, SMEM_BYTES>>>(out);
}